// round 9
// baseline (speedup 1.0000x reference)
#include <cuda_runtime.h>
#include <cstdint>

// Embedding gather, persistent warp-autonomous version (sm_103a).
// x: [32768] int32; emb: [50257, 512] f32; out: [32768, 512] f32.
// even ids -> id 0 (reference: jnp.where(x % 2 == 0, 0, x)).
//
// Each WARP independently grid-strides over row pairs (2 rows = 4KB).
// Ids via shfl broadcast (no smem, no __syncthreads). Iterations are
// independent, so ptxas can software-pipeline loads of pair i+1 over
// stores of pair i: continuous ~16 LDG.128 in flight per warp, no
// per-CTA prologue/ramp, no wave-tail quantization.

static constexpr int VEC_PER_ROW = 128;   // float4 per row
static constexpr int THREADS     = 256;   // 8 warps per CTA
static constexpr int CTAS        = 296;   // 2 per SM (148 SMs)

__global__ __launch_bounds__(THREADS)
void embed_gather_kernel(const int* __restrict__ x,
                         const float4* __restrict__ emb,
                         float4* __restrict__ out,
                         int n_pairs) {
    const int lane   = threadIdx.x & 31;
    const int warp   = (blockIdx.x * THREADS + threadIdx.x) >> 5;
    const int nwarps = (gridDim.x * THREADS) >> 5;

#pragma unroll 2
    for (int p = warp; p < n_pairs; p += nwarps) {
        // Rows 2p, 2p+1. Lanes 0,1 fetch the two token ids; broadcast.
        int tok = 0;
        if (lane < 2) {
            tok = x[2 * p + lane];
            tok = (tok & 1) ? tok : 0;   // even ids -> row 0
        }
        const int id0 = __shfl_sync(0xffffffffu, tok, 0);
        const int id1 = __shfl_sync(0xffffffffu, tok, 1);

        const float4* s0 = emb + (size_t)id0 * VEC_PER_ROW + lane;
        const float4* s1 = emb + (size_t)id1 * VEC_PER_ROW + lane;

        // 8 independent LDG.128 per lane (4 per row).
        float4 a0 = __ldg(s0 +  0);
        float4 a1 = __ldg(s0 + 32);
        float4 a2 = __ldg(s0 + 64);
        float4 a3 = __ldg(s0 + 96);
        float4 b0 = __ldg(s1 +  0);
        float4 b1 = __ldg(s1 + 32);
        float4 b2 = __ldg(s1 + 64);
        float4 b3 = __ldg(s1 + 96);

        float4* d = out + (size_t)(2 * p) * VEC_PER_ROW + lane;
        d[  0] = a0;
        d[ 32] = a1;
        d[ 64] = a2;
        d[ 96] = a3;
        d[128] = b0;
        d[160] = b1;
        d[192] = b2;
        d[224] = b3;
    }
}

extern "C" void kernel_launch(void* const* d_in, const int* in_sizes, int n_in,
                              void* d_out, int out_size) {
    const int* x      = (const int*)d_in[0];
    const float4* emb = (const float4*)d_in[1];
    float4* out       = (float4*)d_out;

    int n_rows  = in_sizes[0];      // 32768
    int n_pairs = n_rows >> 1;      // 16384 (n_rows is even)

    embed_gather_kernel<<<CTAS, THREADS>>>(x, emb, out, n_pairs);
}